// round 11
// baseline (speedup 1.0000x reference)
#include <cuda_runtime.h>
#include <cuda_bf16.h>
#include <cstdint>

#define Bb 32
#define Cc 8
#define Ll 4096
#define Kk 128
#define Ss 64
#define Ww (Ll - Ss + 1)          /* 4033 */
#define WT 64                     /* windows per CTA */
#define NWT ((Ww + WT - 1) / WT)  /* 64 */
#define RPB 144                   /* A row pitch bytes (128 data + 16 pad) */

/* smem layout (bytes) */
#define OFF_A(p)  ((p) * 18432)               /* 128 x 144 per buffer */
#define OFF_XE(p) (36864 + (p) * 1536)        /* 208 bf16 even-aligned seg */
#define OFF_XO(p) (OFF_XE(p) + 448)           /* +448 == 64 mod 128: bank-split */
#define OFF_XN(p) (OFF_XE(p) + 896)           /* 64 f32 window norms */
#define OFF_SN    (36864 + 3072)              /* 1024 f32 shapelet norms */
#define SMEM_BYTES (OFF_SN + Cc * Kk * 4)     /* 44032 */

__device__ __nv_bfloat16 g_xb[Bb * Cc * Ll];
__device__ __nv_bfloat16 g_shb[Cc * Kk * Ss];
__device__ float         g_sn[Cc * Kk];

__device__ __forceinline__ uint32_t smem_u32(const void* p) {
    uint32_t a;
    asm("{ .reg .u64 t; cvta.to.shared.u64 t, %1; cvt.u32.u64 %0, t; }" : "=r"(a) : "l"(p));
    return a;
}
__device__ __forceinline__ void cp_async16(uint32_t dst, const void* src) {
    asm volatile("cp.async.ca.shared.global [%0], [%1], 16;" :: "r"(dst), "l"(src) : "memory");
}
__device__ __forceinline__ void cp_async_commit() {
    asm volatile("cp.async.commit_group;" ::: "memory");
}
__device__ __forceinline__ void cp_async_wait0() {
    asm volatile("cp.async.wait_group 0;" ::: "memory");
}
__device__ __forceinline__ float sqrt_approx(float v) {
    float r;
    asm("sqrt.approx.f32 %0, %1;" : "=f"(r) : "f"(v));
    return r;
}
__device__ __forceinline__ void ldsm_x4(uint32_t* r, uint32_t addr) {
    asm volatile("ldmatrix.sync.aligned.m8n8.x4.shared.b16 {%0,%1,%2,%3}, [%4];"
                 : "=r"(r[0]), "=r"(r[1]), "=r"(r[2]), "=r"(r[3]) : "r"(addr));
}
__device__ __forceinline__ void mma_bf16(float* c, const uint32_t* a, uint32_t b0, uint32_t b1) {
    asm volatile("mma.sync.aligned.m16n8k16.row.col.f32.bf16.bf16.f32 "
                 "{%0,%1,%2,%3}, {%4,%5,%6,%7}, {%8,%9}, {%0,%1,%2,%3};"
                 : "+f"(c[0]), "+f"(c[1]), "+f"(c[2]), "+f"(c[3])
                 : "r"(a[0]), "r"(a[1]), "r"(a[2]), "r"(a[3]), "r"(b0), "r"(b1));
}

/* ---- prep kernels ---- */
__global__ void prep_x_kernel(const float* __restrict__ x) {
    int i = blockIdx.x * blockDim.x + threadIdx.x;
    if (i < Bb * Cc * Ll) g_xb[i] = __float2bfloat16(x[i]);
}
__global__ void prep_sh_kernel(const float* __restrict__ sh, float* __restrict__ out) {
    int i = blockIdx.x * blockDim.x + threadIdx.x;
    if (i < Bb * Kk) out[i] = __int_as_float(0x7f7fffff); /* FLT_MAX */
    if (i < Cc * Kk) {
        float s = 0.0f;
        #pragma unroll 8
        for (int j = 0; j < Ss; j++) {
            float v = sh[i * Ss + j];
            g_shb[i * Ss + j] = __float2bfloat16(v);
            s = fmaf(v, v, s);
        }
        g_sn[i] = s;
    }
}

/* ---- main kernel ---- */
__global__ void __launch_bounds__(256, 2)
shapelet_bf16_kernel(const float* __restrict__ x, float* __restrict__ out) {
    extern __shared__ float sm[];
    char* smc = (char*)sm;
    const uint32_t sb = smem_u32(sm);
    const int tid = threadIdx.x;
    const int lane = tid & 31;
    const int wid = tid >> 5;
    const int b = blockIdx.y;
    const int w0 = blockIdx.x * WT;
    const int kwarp = wid >> 1;   /* 0..3: 32 k-rows */
    const int wwarp = wid & 1;    /* 0..1: 32 w-cols */
    const int gid = lane >> 2;    /* 0..7 */
    const int qid = lane & 3;     /* 0..3 */

    /* preload shapelet norms (exact fp32) */
    #pragma unroll
    for (int i = tid; i < Cc * Kk; i += 256) ((float*)(smc + OFF_SN))[i] = g_sn[i];

    float dist[2][4][4];
    #pragma unroll
    for (int mi = 0; mi < 2; mi++)
        #pragma unroll
        for (int ni = 0; ni < 4; ni++)
            #pragma unroll
            for (int v = 0; v < 4; v++) dist[mi][ni][v] = 0.0f;

    /* per-thread constant addresses */
    const uint32_t aRow = (uint32_t)((kwarp * 32 + (lane & 15)) * RPB + ((lane & 16) ? 16 : 0));
    const int a_row8 = tid >> 3;          /* cp.async row stripe */
    const int a_v8   = tid & 7;
    const int bOffB  = (wwarp * 32 + gid + 2 * qid) * 2;  /* B frag byte base */
    const int xoSel  = (gid & 1);                          /* odd-parity lane */
    const int cbase  = wwarp * 32 + 2 * qid;
    const int r0base = kwarp * 32 + gid;

    /* ---------- stage channel 0 into buffer 0 ---------- */
    {
        const __nv_bfloat16* shc = g_shb;
        #pragma unroll
        for (int it = 0; it < 4; it++) {
            int row = it * 32 + a_row8;
            cp_async16(sb + OFF_A(0) + row * RPB + a_v8 * 16, shc + row * Ss + a_v8 * 8);
        }
        cp_async_commit();
        const __nv_bfloat16* xbrow = g_xb + (b * Cc + 0) * Ll;
        if (tid < 208) {
            int g = w0 + tid;
            *(__nv_bfloat16*)(smc + OFF_XE(0) + tid * 2) =
                (g < Ll) ? xbrow[g] : __float2bfloat16(0.0f);
            *(__nv_bfloat16*)(smc + OFF_XO(0) + tid * 2) =
                (g + 1 < Ll) ? xbrow[g + 1] : __float2bfloat16(0.0f);
        }
        if (tid < WT) {
            const float* xrow = x + (b * Cc + 0) * Ll;
            int w = w0 + tid;
            float t = 0.0f;
            #pragma unroll 16
            for (int s = 0; s < Ss; s++) {
                float v = (w + s < Ll) ? xrow[w + s] : 0.0f;
                t = fmaf(v, v, t);
            }
            ((float*)(smc + OFF_XN(0)))[tid] = t;
        }
    }
    cp_async_wait0();
    __syncthreads();

    #pragma unroll 1
    for (int cc = 0; cc < Cc; cc++) {
        const int p = cc & 1;

        /* ---------- stage channel cc+1 into the other buffer ---------- */
        if (cc < Cc - 1) {
            const __nv_bfloat16* shc = g_shb + (cc + 1) * Kk * Ss;
            #pragma unroll
            for (int it = 0; it < 4; it++) {
                int row = it * 32 + a_row8;
                cp_async16(sb + OFF_A(p ^ 1) + row * RPB + a_v8 * 16, shc + row * Ss + a_v8 * 8);
            }
            cp_async_commit();
            const __nv_bfloat16* xbrow = g_xb + (b * Cc + cc + 1) * Ll;
            if (tid < 208) {
                int g = w0 + tid;
                *(__nv_bfloat16*)(smc + OFF_XE(p ^ 1) + tid * 2) =
                    (g < Ll) ? xbrow[g] : __float2bfloat16(0.0f);
                *(__nv_bfloat16*)(smc + OFF_XO(p ^ 1) + tid * 2) =
                    (g + 1 < Ll) ? xbrow[g + 1] : __float2bfloat16(0.0f);
            }
            if (tid < WT) {
                const float* xrow = x + (b * Cc + cc + 1) * Ll;
                int w = w0 + tid;
                float t = 0.0f;
                #pragma unroll 16
                for (int s = 0; s < Ss; s++) {
                    float v = (w + s < Ll) ? xrow[w + s] : 0.0f;
                    t = fmaf(v, v, t);
                }
                ((float*)(smc + OFF_XN(p ^ 1)))[tid] = t;
            }
        }

        /* ---------- compute channel cc from buffer p ---------- */
        float acc[2][4][4];
        #pragma unroll
        for (int mi = 0; mi < 2; mi++)
            #pragma unroll
            for (int ni = 0; ni < 4; ni++)
                #pragma unroll
                for (int v = 0; v < 4; v++) acc[mi][ni][v] = 0.0f;

        const uint32_t aAddr = sb + OFF_A(p) + aRow;
        /* parity-selected x-segment base: odd lanes read the +1-shifted copy */
        const char* xb = smc + (xoSel ? (OFF_XO(p) - 2) : OFF_XE(p));

        #pragma unroll
        for (int ks = 0; ks < 4; ks++) {
            uint32_t A0[4], A1[4];
            ldsm_x4(A0, aAddr + ks * 32);
            ldsm_x4(A1, aAddr + 16 * RPB + ks * 32);
            #pragma unroll
            for (int ni = 0; ni < 4; ni++) {
                int bo = bOffB + ni * 16 + ks * 32;
                uint32_t b0 = *(const uint32_t*)(xb + bo);
                uint32_t b1 = *(const uint32_t*)(xb + bo + 16);
                mma_bf16(acc[0][ni], A0, b0, b1);
                mma_bf16(acc[1][ni], A1, b0, b1);
            }
        }

        /* epilogue: d2 = xn + sn - 2*cross; dist += sqrt(d2) */
        const float* xn = (const float*)(smc + OFF_XN(p));
        const float* sn = (const float*)(smc + OFF_SN);
        #pragma unroll
        for (int ni = 0; ni < 4; ni++) {
            float x0 = xn[cbase + ni * 8];
            float x1 = xn[cbase + ni * 8 + 1];
            #pragma unroll
            for (int mi = 0; mi < 2; mi++) {
                float sn0 = sn[cc * Kk + r0base + mi * 16];
                float sn1 = sn[cc * Kk + r0base + mi * 16 + 8];
                float d0 = fmaxf(fmaf(-2.0f, acc[mi][ni][0], x0 + sn0), 1e-12f);
                float d1 = fmaxf(fmaf(-2.0f, acc[mi][ni][1], x1 + sn0), 1e-12f);
                float d2 = fmaxf(fmaf(-2.0f, acc[mi][ni][2], x0 + sn1), 1e-12f);
                float d3 = fmaxf(fmaf(-2.0f, acc[mi][ni][3], x1 + sn1), 1e-12f);
                dist[mi][ni][0] += sqrt_approx(d0);
                dist[mi][ni][1] += sqrt_approx(d1);
                dist[mi][ni][2] += sqrt_approx(d2);
                dist[mi][ni][3] += sqrt_approx(d3);
            }
        }
        cp_async_wait0();
        __syncthreads();
    }

    /* ---- min over valid windows, lane reduce over qid, global atomicMin ---- */
    const float INF = __int_as_float(0x7f800000);
    #pragma unroll
    for (int mi = 0; mi < 2; mi++) {
        float m0 = INF, m1 = INF;
        #pragma unroll
        for (int ni = 0; ni < 4; ni++) {
            int wv = w0 + cbase + ni * 8;
            if (wv < Ww)     { m0 = fminf(m0, dist[mi][ni][0]); m1 = fminf(m1, dist[mi][ni][2]); }
            if (wv + 1 < Ww) { m0 = fminf(m0, dist[mi][ni][1]); m1 = fminf(m1, dist[mi][ni][3]); }
        }
        m0 = fminf(m0, __shfl_xor_sync(0xFFFFFFFF, m0, 1));
        m0 = fminf(m0, __shfl_xor_sync(0xFFFFFFFF, m0, 2));
        m1 = fminf(m1, __shfl_xor_sync(0xFFFFFFFF, m1, 1));
        m1 = fminf(m1, __shfl_xor_sync(0xFFFFFFFF, m1, 2));
        if (qid == 0) {
            int r = r0base + mi * 16;
            atomicMin((int*)&out[b * Kk + r],     __float_as_int(m0));
            atomicMin((int*)&out[b * Kk + r + 8], __float_as_int(m1));
        }
    }
}

extern "C" void kernel_launch(void* const* d_in, const int* in_sizes, int n_in,
                              void* d_out, int out_size) {
    const float* x  = (const float*)d_in[0];   /* (32, 8, 4096) */
    const float* sh = (const float*)d_in[1];   /* (8, 128, 64)  */
    float* out = (float*)d_out;                /* (32, 1, 128)  */

    cudaFuncSetAttribute(shapelet_bf16_kernel,
                         cudaFuncAttributeMaxDynamicSharedMemorySize, SMEM_BYTES);

    prep_x_kernel<<<(Bb * Cc * Ll + 255) / 256, 256>>>(x);
    prep_sh_kernel<<<(Bb * Kk + 255) / 256, 256>>>(sh, out);

    dim3 grid(NWT, Bb);
    shapelet_bf16_kernel<<<grid, 256, SMEM_BYTES>>>(x, out);
}

// round 12
// speedup vs baseline: 1.3022x; 1.3022x over previous
#include <cuda_runtime.h>
#include <cuda_bf16.h>
#include <cstdint>

#define Bb 32
#define Cc 8
#define Ll 4096
#define Kk 128
#define Ss 64
#define Ww (Ll - Ss + 1)          /* 4033 */
#define WT 64                     /* windows per CTA */
#define NWT ((Ww + WT - 1) / WT)  /* 64 */
#define RPB 144                   /* A row pitch bytes (128 data + 16 pad) */

/* smem layout (bytes) */
#define OFF_A(p)  ((p) * 18432)               /* 128 x 144 per buffer */
#define OFF_XE(p) (36864 + (p) * 1536)        /* 208 bf16 even-aligned seg */
#define OFF_XO(p) (OFF_XE(p) + 448)           /* +448 == 64 mod 128: bank-split */
#define OFF_XN(p) (OFF_XE(p) + 896)           /* 64 f32 window norms */
#define OFF_SN    (36864 + 3072)              /* 1024 f32 shapelet norms */
#define SMEM_BYTES (OFF_SN + Cc * Kk * 4)     /* 44032 */

__device__ __nv_bfloat16 g_shb[Cc * Kk * Ss];
__device__ float         g_sn[Cc * Kk];
__device__ float         g_xn[Bb * Cc * Ww];  /* precomputed window norms */

__device__ __forceinline__ uint32_t smem_u32(const void* p) {
    uint32_t a;
    asm("{ .reg .u64 t; cvta.to.shared.u64 t, %1; cvt.u32.u64 %0, t; }" : "=r"(a) : "l"(p));
    return a;
}
__device__ __forceinline__ void cp_async16(uint32_t dst, const void* src) {
    asm volatile("cp.async.ca.shared.global [%0], [%1], 16;" :: "r"(dst), "l"(src) : "memory");
}
__device__ __forceinline__ void cp_async_commit() {
    asm volatile("cp.async.commit_group;" ::: "memory");
}
__device__ __forceinline__ void cp_async_wait0() {
    asm volatile("cp.async.wait_group 0;" ::: "memory");
}
__device__ __forceinline__ float sqrt_approx(float v) {
    float r;
    asm("sqrt.approx.f32 %0, %1;" : "=f"(r) : "f"(v));
    return r;
}
__device__ __forceinline__ void ldsm_x4(uint32_t* r, uint32_t addr) {
    asm volatile("ldmatrix.sync.aligned.m8n8.x4.shared.b16 {%0,%1,%2,%3}, [%4];"
                 : "=r"(r[0]), "=r"(r[1]), "=r"(r[2]), "=r"(r[3]) : "r"(addr));
}
__device__ __forceinline__ void mma_bf16(float* c, const uint32_t* a, uint32_t b0, uint32_t b1) {
    asm volatile("mma.sync.aligned.m16n8k16.row.col.f32.bf16.bf16.f32 "
                 "{%0,%1,%2,%3}, {%4,%5,%6,%7}, {%8,%9}, {%0,%1,%2,%3};"
                 : "+f"(c[0]), "+f"(c[1]), "+f"(c[2]), "+f"(c[3])
                 : "r"(a[0]), "r"(a[1]), "r"(a[2]), "r"(a[3]), "r"(b0), "r"(b1));
}

/* ---- prep kernels ---- */
__global__ void xnorm_kernel(const float* __restrict__ x) {
    int w = blockIdx.x * blockDim.x + threadIdx.x;
    int row = blockIdx.y;                       /* b*Cc + c */
    if (w < Ww) {
        const float* xr = x + row * Ll;
        float t = 0.0f;
        #pragma unroll 16
        for (int s = 0; s < Ss; s++) { float v = xr[w + s]; t = fmaf(v, v, t); }
        g_xn[row * Ww + w] = t;
    }
}
__global__ void prep_sh_kernel(const float* __restrict__ sh, float* __restrict__ out) {
    int i = blockIdx.x * blockDim.x + threadIdx.x;
    if (i < Bb * Kk) out[i] = __int_as_float(0x7f7fffff); /* FLT_MAX */
    if (i < Cc * Kk) {
        float s = 0.0f;
        #pragma unroll 8
        for (int j = 0; j < Ss; j++) {
            float v = sh[i * Ss + j];
            g_shb[i * Ss + j] = __float2bfloat16(v);
            s = fmaf(v, v, s);
        }
        g_sn[i] = s;
    }
}

/* ---- main kernel ---- */
__global__ void __launch_bounds__(256, 2)
shapelet_bf16_kernel(const float* __restrict__ x, float* __restrict__ out) {
    extern __shared__ float sm[];
    char* smc = (char*)sm;
    const uint32_t sb = smem_u32(sm);
    const int tid = threadIdx.x;
    const int lane = tid & 31;
    const int wid = tid >> 5;
    const int b = blockIdx.y;
    const int w0 = blockIdx.x * WT;
    const int kwarp = wid >> 1;   /* 0..3: 32 k-rows */
    const int wwarp = wid & 1;    /* 0..1: 32 w-cols */
    const int gid = lane >> 2;    /* 0..7 */
    const int qid = lane & 3;     /* 0..3 */

    /* preload shapelet norms (exact fp32) */
    #pragma unroll
    for (int i = tid; i < Cc * Kk; i += 256) ((float*)(smc + OFF_SN))[i] = g_sn[i];

    float dist[2][4][4];
    #pragma unroll
    for (int mi = 0; mi < 2; mi++)
        #pragma unroll
        for (int ni = 0; ni < 4; ni++)
            #pragma unroll
            for (int v = 0; v < 4; v++) dist[mi][ni][v] = 0.0f;

    /* per-thread constant addresses */
    const uint32_t aRow = (uint32_t)((kwarp * 32 + (lane & 15)) * RPB + ((lane & 16) ? 16 : 0));
    const int a_row8 = tid >> 3;          /* cp.async row stripe */
    const int a_v8   = tid & 7;
    const int bOffB  = (wwarp * 32 + gid + 2 * qid) * 2;  /* B frag byte base */
    const int xoSel  = (gid & 1);                          /* odd-parity lane */
    const int cbase  = wwarp * 32 + 2 * qid;
    const int r0base = kwarp * 32 + gid;

    /* ---------- stage channel 0 into buffer 0 ---------- */
    {
        #pragma unroll
        for (int it = 0; it < 4; it++) {
            int row = it * 32 + a_row8;
            cp_async16(sb + OFF_A(0) + row * RPB + a_v8 * 16, g_shb + row * Ss + a_v8 * 8);
        }
        cp_async_commit();
        const float* xrow = x + (b * Cc + 0) * Ll;
        if (tid < 208) {
            int g = w0 + tid;
            float v0 = (g < Ll) ? xrow[g] : 0.0f;
            float v1 = (g + 1 < Ll) ? xrow[g + 1] : 0.0f;
            *(__nv_bfloat16*)(smc + OFF_XE(0) + tid * 2) = __float2bfloat16(v0);
            *(__nv_bfloat16*)(smc + OFF_XO(0) + tid * 2) = __float2bfloat16(v1);
        }
        if (tid < WT) {
            int w = w0 + tid;
            ((float*)(smc + OFF_XN(0)))[tid] =
                (w < Ww) ? g_xn[(b * Cc + 0) * Ww + w] : 0.0f;
        }
    }
    cp_async_wait0();
    __syncthreads();

    #pragma unroll 1
    for (int cc = 0; cc < Cc; cc++) {
        const int p = cc & 1;

        /* ---------- stage channel cc+1 into the other buffer ---------- */
        if (cc < Cc - 1) {
            const __nv_bfloat16* shc = g_shb + (cc + 1) * Kk * Ss;
            #pragma unroll
            for (int it = 0; it < 4; it++) {
                int row = it * 32 + a_row8;
                cp_async16(sb + OFF_A(p ^ 1) + row * RPB + a_v8 * 16, shc + row * Ss + a_v8 * 8);
            }
            cp_async_commit();
            const float* xrow = x + (b * Cc + cc + 1) * Ll;
            if (tid < 208) {
                int g = w0 + tid;
                float v0 = (g < Ll) ? xrow[g] : 0.0f;
                float v1 = (g + 1 < Ll) ? xrow[g + 1] : 0.0f;
                *(__nv_bfloat16*)(smc + OFF_XE(p ^ 1) + tid * 2) = __float2bfloat16(v0);
                *(__nv_bfloat16*)(smc + OFF_XO(p ^ 1) + tid * 2) = __float2bfloat16(v1);
            }
            if (tid < WT) {
                int w = w0 + tid;
                ((float*)(smc + OFF_XN(p ^ 1)))[tid] =
                    (w < Ww) ? g_xn[(b * Cc + cc + 1) * Ww + w] : 0.0f;
            }
        }

        /* ---------- compute channel cc from buffer p ---------- */
        float acc[2][4][4];
        #pragma unroll
        for (int mi = 0; mi < 2; mi++)
            #pragma unroll
            for (int ni = 0; ni < 4; ni++)
                #pragma unroll
                for (int v = 0; v < 4; v++) acc[mi][ni][v] = 0.0f;

        const uint32_t aAddr = sb + OFF_A(p) + aRow;
        /* parity-selected x-segment base: odd lanes read the +1-shifted copy */
        const char* xb = smc + (xoSel ? (OFF_XO(p) - 2) : OFF_XE(p));

        #pragma unroll
        for (int ks = 0; ks < 4; ks++) {
            uint32_t A0[4], A1[4];
            ldsm_x4(A0, aAddr + ks * 32);
            ldsm_x4(A1, aAddr + 16 * RPB + ks * 32);
            #pragma unroll
            for (int ni = 0; ni < 4; ni++) {
                int bo = bOffB + ni * 16 + ks * 32;
                uint32_t b0 = *(const uint32_t*)(xb + bo);
                uint32_t b1 = *(const uint32_t*)(xb + bo + 16);
                mma_bf16(acc[0][ni], A0, b0, b1);
                mma_bf16(acc[1][ni], A1, b0, b1);
            }
        }

        /* epilogue: d2 = xn + sn - 2*cross; dist += sqrt(d2) */
        const float* xn = (const float*)(smc + OFF_XN(p));
        const float* sn = (const float*)(smc + OFF_SN);
        #pragma unroll
        for (int ni = 0; ni < 4; ni++) {
            float x0 = xn[cbase + ni * 8];
            float x1 = xn[cbase + ni * 8 + 1];
            #pragma unroll
            for (int mi = 0; mi < 2; mi++) {
                float sn0 = sn[cc * Kk + r0base + mi * 16];
                float sn1 = sn[cc * Kk + r0base + mi * 16 + 8];
                float d0 = fmaxf(fmaf(-2.0f, acc[mi][ni][0], x0 + sn0), 1e-12f);
                float d1 = fmaxf(fmaf(-2.0f, acc[mi][ni][1], x1 + sn0), 1e-12f);
                float d2 = fmaxf(fmaf(-2.0f, acc[mi][ni][2], x0 + sn1), 1e-12f);
                float d3 = fmaxf(fmaf(-2.0f, acc[mi][ni][3], x1 + sn1), 1e-12f);
                dist[mi][ni][0] += sqrt_approx(d0);
                dist[mi][ni][1] += sqrt_approx(d1);
                dist[mi][ni][2] += sqrt_approx(d2);
                dist[mi][ni][3] += sqrt_approx(d3);
            }
        }
        cp_async_wait0();
        __syncthreads();
    }

    /* ---- min over valid windows, lane reduce over qid, global atomicMin ---- */
    const float INF = __int_as_float(0x7f800000);
    #pragma unroll
    for (int mi = 0; mi < 2; mi++) {
        float m0 = INF, m1 = INF;
        #pragma unroll
        for (int ni = 0; ni < 4; ni++) {
            int wv = w0 + cbase + ni * 8;
            if (wv < Ww)     { m0 = fminf(m0, dist[mi][ni][0]); m1 = fminf(m1, dist[mi][ni][2]); }
            if (wv + 1 < Ww) { m0 = fminf(m0, dist[mi][ni][1]); m1 = fminf(m1, dist[mi][ni][3]); }
        }
        m0 = fminf(m0, __shfl_xor_sync(0xFFFFFFFF, m0, 1));
        m0 = fminf(m0, __shfl_xor_sync(0xFFFFFFFF, m0, 2));
        m1 = fminf(m1, __shfl_xor_sync(0xFFFFFFFF, m1, 1));
        m1 = fminf(m1, __shfl_xor_sync(0xFFFFFFFF, m1, 2));
        if (qid == 0) {
            int r = r0base + mi * 16;
            atomicMin((int*)&out[b * Kk + r],     __float_as_int(m0));
            atomicMin((int*)&out[b * Kk + r + 8], __float_as_int(m1));
        }
    }
}

extern "C" void kernel_launch(void* const* d_in, const int* in_sizes, int n_in,
                              void* d_out, int out_size) {
    const float* x  = (const float*)d_in[0];   /* (32, 8, 4096) */
    const float* sh = (const float*)d_in[1];   /* (8, 128, 64)  */
    float* out = (float*)d_out;                /* (32, 1, 128)  */

    cudaFuncSetAttribute(shapelet_bf16_kernel,
                         cudaFuncAttributeMaxDynamicSharedMemorySize, SMEM_BYTES);

    dim3 xg((Ww + 255) / 256, Bb * Cc);
    xnorm_kernel<<<xg, 256>>>(x);
    prep_sh_kernel<<<(Bb * Kk + 255) / 256, 256>>>(sh, out);

    dim3 grid(NWT, Bb);
    shapelet_bf16_kernel<<<grid, 256, SMEM_BYTES>>>(x, out);
}